// round 16
// baseline (speedup 1.0000x reference)
#include <cuda_runtime.h>
#include <math.h>
#include <stdint.h>

#define S_LEN 2048
#define NH 16
#define HD 64
#define DM 1024
#define BB 2
#define M_TOK (BB * S_LEN)   // 4096
#define VP (S_LEN / 2)       // uint2 per V d-row

// -------- scratch (static device globals; allocation-free) --------
__device__ uint32_t g_hid_p[(size_t)M_TOK * DM];     // hidden, tf32 paired
__device__ uint32_t g_wqkv_p[(size_t)3 * DM * DM];   // w_qkv, tf32 paired
__device__ uint32_t g_wout_p[(size_t)DM * DM];       // w_out, tf32 paired
__device__ float    g_q [(size_t)M_TOK * DM];        // [B,H,S,Dh] f32
__device__ uint32_t g_ks[(size_t)M_TOK * DM];        // K tf32 hi, d-paired rows
__device__ uint32_t g_vt[(size_t)M_TOK * DM];        // V^T tf32, key-paired
__device__ uint32_t g_ao[(size_t)M_TOK * DM];        // attn out, tf32 paired
__device__ float    g_part[2][(size_t)M_TOK * DM];   // out-proj K-split partials
__device__ int      g_len[BB];

__device__ __forceinline__ uint32_t f2tf32(float f) {
    uint32_t r;
    asm("cvt.rna.tf32.f32 %0, %1;" : "=r"(r) : "f"(f));
    return r;
}

#define MMA_TF32(c, a, b0, b1)                                              \
    asm volatile(                                                           \
        "mma.sync.aligned.m16n8k8.row.col.f32.tf32.tf32.f32 "               \
        "{%0,%1,%2,%3}, {%4,%5,%6,%7}, {%8,%9}, {%0,%1,%2,%3};"             \
        : "+f"((c)[0]), "+f"((c)[1]), "+f"((c)[2]), "+f"((c)[3])            \
        : "r"((a)[0]), "r"((a)[1]), "r"((a)[2]), "r"((a)[3]),               \
          "r"(b0), "r"(b1))

__device__ __forceinline__ void cpa16(void* smem, const void* gmem) {
    uint32_t s = (uint32_t)__cvta_generic_to_shared(smem);
    asm volatile("cp.async.cg.shared.global [%0], [%1], 16;" :: "r"(s), "l"(gmem));
}
#define CPA_COMMIT() asm volatile("cp.async.commit_group;")
#define CPA_WAIT1()  asm volatile("cp.async.wait_group 1;")
#define CPA_WAIT2()  asm volatile("cp.async.wait_group 2;")

// ============================================================
// Mask length extraction — dtype-agnostic (prefix-true mask).
// ============================================================
__global__ void compute_lens(const void* __restrict__ mask)
{
    __shared__ int cnt;
    const int b = blockIdx.x;
    if (threadIdx.x == 0) cnt = 0;
    __syncthreads();

    const unsigned char* bytes = (const unsigned char*)mask;
    int dtype;
    if (*(const float*)mask == 1.0f) dtype = 2;
    else if (bytes[0] == 1 && bytes[1] == 0) dtype = 1;
    else dtype = 0;

    int local = 0;
    for (int s = threadIdx.x; s < S_LEN; s += blockDim.x) {
        int v;
        if (dtype == 2)      v = (((const float*)mask)[b * S_LEN + s] != 0.0f);
        else if (dtype == 1) v = (((const int*)mask)[b * S_LEN + s] != 0);
        else                 v = (bytes[b * S_LEN + s] != 0);
        local += v;
    }
    atomicAdd(&cnt, local);
    __syncthreads();
    if (threadIdx.x == 0) g_len[b] = cnt;
}

// ============================================================
// Single fused converter: f32 -> paired tf32 for all 3 operands.
// ============================================================
#define CVT_N1 (M_TOK * DM)
#define CVT_N2 (3 * DM * DM)
#define CVT_N3 (DM * DM)

__global__ void cvt_pair_all(const float* __restrict__ h,
                             const float* __restrict__ wq,
                             const float* __restrict__ wo,
                             uint32_t* __restrict__ hp,
                             uint32_t* __restrict__ wqp,
                             uint32_t* __restrict__ wop)
{
    int idx = blockIdx.x * blockDim.x + threadIdx.x;
    const float* in; uint32_t* out; int i;
    if (idx < CVT_N1)                 { in = h;  out = hp;  i = idx; }
    else if (idx < CVT_N1 + CVT_N2)   { in = wq; out = wqp; i = idx - CVT_N1; }
    else if (idx < CVT_N1 + CVT_N2 + CVT_N3)
                                      { in = wo; out = wop; i = idx - CVT_N1 - CVT_N2; }
    else return;
    int blk = i >> 3, p = i & 7;
    int c = (p & 1) ? ((p >> 1) + 4) : (p >> 1);
    out[i] = f2tf32(in[(size_t)blk * 8 + c]);
}

// ============================================================
// Paired-tf32 GEMM body: 128x64 block, 128 thr, 2-stage, BK=64
// (8 k8-steps = 128 mma between sync pairs). 2 CTAs/SM.
// smem row stride 36 uint2 (32 data + 4 pad) -> conflict-free LDS.64.
// ============================================================
#define GSPW 36   // uint2 per smem row (BK=64)

struct GemmCtx {
    float c[4][4][4];
    int bm, bn, wm, wn, lr, lc;
};

template <typename EPI>
__device__ __forceinline__ void gemm_tf32p_body(
    const uint32_t* __restrict__ A, const uint32_t* __restrict__ B,
    int Kloop, int Kstr, uint2* As, uint2* Bs, EPI epi)
{
    const int bm = blockIdx.y * 128;
    const int bn = blockIdx.x * 64;
    const int tid = threadIdx.x;
    const int wid = tid >> 5;
    const int lane = tid & 31;
    const int wm = (wid & 1) * 64;
    const int wn = (wid >> 1) * 32;
    const int lr = lane >> 2;
    const int lc = lane & 3;

    GemmCtx g;
    g.bm = bm; g.bn = bn; g.wm = wm; g.wn = wn; g.lr = lr; g.lc = lc;
#pragma unroll
    for (int i = 0; i < 4; i++)
#pragma unroll
        for (int j = 0; j < 4; j++)
#pragma unroll
            for (int r = 0; r < 4; r++) g.c[i][j][r] = 0.f;

    // per stage: A 128 rows x 16 chunks = 2048, B 64 x 16 = 1024 -> 24/thread
    auto issue = [&](int st, int k0 /*u32 units*/) {
#pragma unroll
        for (int i = 0; i < 16; i++) {
            int cid = tid + i * 128;          // 0..2047
            int row = cid >> 4;
            int cc  = (cid & 15) * 2;         // uint2 col
            cpa16(&As[st * 128 * GSPW + row * GSPW + cc],
                  &A[(size_t)(bm + row) * Kstr + k0 + cc * 2]);
        }
#pragma unroll
        for (int i = 0; i < 8; i++) {
            int cid = tid + i * 128;          // 0..1023
            int row = cid >> 4;
            int cc  = (cid & 15) * 2;
            cpa16(&Bs[st * 64 * GSPW + row * GSPW + cc],
                  &B[(size_t)(bn + row) * Kstr + k0 + cc * 2]);
        }
        CPA_COMMIT();
    };

    const int nIt = Kloop / 64;
    issue(0, 0);

    for (int it = 0; it < nIt; it++) {
        const int st = it & 1;
        if (it + 1 < nIt) issue(st ^ 1, (it + 1) * 64);
        else CPA_COMMIT();
        CPA_WAIT1();
        __syncthreads();

        const uint2* Asb = As + st * 128 * GSPW;
        const uint2* Bsb = Bs + st * 64 * GSPW;
#pragma unroll
        for (int ks = 0; ks < 8; ks++) {
            uint32_t af[4][4], bf[4][2];
#pragma unroll
            for (int mf = 0; mf < 4; mf++) {
                int r0 = wm + mf * 16 + lr;
                uint2 x = Asb[(r0    ) * GSPW + ks * 4 + lc];
                uint2 y = Asb[(r0 + 8) * GSPW + ks * 4 + lc];
                af[mf][0] = x.x; af[mf][1] = y.x;
                af[mf][2] = x.y; af[mf][3] = y.y;
            }
#pragma unroll
            for (int nf = 0; nf < 4; nf++) {
                uint2 z = Bsb[(wn + nf * 8 + lr) * GSPW + ks * 4 + lc];
                bf[nf][0] = z.x; bf[nf][1] = z.y;
            }
#pragma unroll
            for (int mf = 0; mf < 4; mf++)
#pragma unroll
                for (int nf = 0; nf < 4; nf++)
                    MMA_TF32(g.c[mf][nf], af[mf], bf[nf][0], bf[nf][1]);
        }
        __syncthreads();
    }
    epi(g);
}

#define GEMM_SMEM_A (2 * 128 * GSPW)
#define GEMM_SMEM_B (2 * 64 * GSPW)

// ---- out-projection, K-split over blockIdx.z (deterministic) ----
__global__ __launch_bounds__(128, 2) void gemm_out_ksplit(
    const uint32_t* __restrict__ A, const uint32_t* __restrict__ B,
    float* __restrict__ P0, float* __restrict__ P1, int N, int K)
{
    __shared__ uint2 As[GEMM_SMEM_A];
    __shared__ uint2 Bs[GEMM_SMEM_B];
    const int z = blockIdx.z;
    const int kh = K / 2;
    float* P = z ? P1 : P0;
    gemm_tf32p_body(A + z * kh, B + z * kh, kh, K, As, Bs, [&](GemmCtx& g) {
#pragma unroll
        for (int mf = 0; mf < 4; mf++)
#pragma unroll
            for (int nf = 0; nf < 4; nf++) {
                int row = g.bm + g.wm + mf * 16 + g.lr;
                int col = g.bn + g.wn + nf * 8 + g.lc * 2;
                *(float2*)&P[(size_t)row * N + col] =
                    make_float2(g.c[mf][nf][0], g.c[mf][nf][1]);
                *(float2*)&P[(size_t)(row + 8) * N + col] =
                    make_float2(g.c[mf][nf][2], g.c[mf][nf][3]);
            }
    });
}

__global__ void add_out(const float* __restrict__ p0,
                        const float* __restrict__ p1,
                        float* __restrict__ out, int n4)
{
    int i = blockIdx.x * blockDim.x + threadIdx.x;
    if (i >= n4) return;
    float4 a = ((const float4*)p0)[i];
    float4 b = ((const float4*)p1)[i];
    ((float4*)out)[i] = make_float4(a.x + b.x, a.y + b.y, a.z + b.z, a.w + b.w);
}

// ---- QKV GEMM with fused RoPE epilogue ----
__global__ __launch_bounds__(128, 2) void gemm_qkv_rope(
    const uint32_t* __restrict__ A, const uint32_t* __restrict__ B,
    const int* __restrict__ pos_xyz,
    float* __restrict__ Q, uint32_t* __restrict__ Ks,
    uint32_t* __restrict__ Vt)
{
    __shared__ uint2 As[GEMM_SMEM_A];
    __shared__ uint2 Bs[GEMM_SMEM_B];
    gemm_tf32p_body(A, B, DM, DM, As, Bs, [&](GemmCtx& g) {
        int   pP[4], hP[4], dP[4], axP[4];
        float invP[4];
#pragma unroll
        for (int nf = 0; nf < 4; nf++) {
            int col = g.bn + g.wn + nf * 8 + g.lc * 2;
            pP[nf] = col >> 10;
            int rem = col & 1023;
            hP[nf] = rem >> 6;
            int d = rem & 63;
            dP[nf] = d;
            int axis, dim, dd;
            if (d < 20)      { axis = 0; dim = 20; dd = d; }
            else if (d < 40) { axis = 1; dim = 20; dd = d - 20; }
            else             { axis = 2; dim = 24; dd = d - 40; }
            axP[nf] = axis;
            invP[nf] = exp2f(-13.287712379549449f * (float)dd / (float)dim);
        }
#pragma unroll
        for (int mf = 0; mf < 4; mf++) {
#pragma unroll
            for (int rr = 0; rr < 2; rr++) {
                int m = g.bm + g.wm + mf * 16 + g.lr + rr * 8;
                int b = m >> 11, s = m & (S_LEN - 1);
#pragma unroll
                for (int nf = 0; nf < 4; nf++) {
                    float c0 = g.c[mf][nf][rr * 2];
                    float c1 = g.c[mf][nf][rr * 2 + 1];
                    int d = dP[nf];          // even
                    int h = hP[nf];
                    int bh = b * NH + h;
                    if (pP[nf] == 2) {
                        int j = s & 7;
                        size_t pairIdx = (size_t)(s >> 3) * 4 + (j & 3);
                        int comp = j >> 2;
                        size_t row0 = (size_t)bh * 64 + d;
                        Vt[((row0       * VP + pairIdx) << 1) + comp] = f2tf32(c0);
                        Vt[(((row0 + 1) * VP + pairIdx) << 1) + comp] = f2tf32(c1);
                    } else {
                        float pos = (float)pos_xyz[m * 3 + axP[nf]];
                        float sn, cs;
                        sincosf(pos * invP[nf], &sn, &cs);
                        float o0 = c0 * cs - c1 * sn;
                        float o1 = c1 * cs + c0 * sn;
                        if (pP[nf] == 0) {
                            size_t o = ((size_t)bh * S_LEN + s) * HD + d;
                            Q[o] = o0; Q[o + 1] = o1;
                        } else {
                            size_t rowb = ((size_t)bh * S_LEN + s) * HD;
                            int j = d & 7, blk = d >> 3;
                            Ks[rowb + blk * 8 + 2 * (j & 3)  + (j >> 2)]  = f2tf32(o0);
                            int j1 = j + 1;
                            Ks[rowb + blk * 8 + 2 * (j1 & 3) + (j1 >> 2)] = f2tf32(o1);
                        }
                    }
                }
            }
        }
    });
}

// ============================================================
// Flash attention (R15 — best flash so far).
// ============================================================
#define FSK2 36
#define FSV2 36
#define FS_PS 76
#define FA_K_U2   (2 * 64 * FSK2)
#define FA_V_U2   (64 * FSV2)
#define FA_PS_U32 (4 * 16 * FS_PS)
#define FA_SMEM_BYTES ((FA_K_U2 + FA_V_U2) * 8 + FA_PS_U32 * 4)

__global__ __launch_bounds__(128, 3) void flash_attn_tf32(
    const float* __restrict__ Q, const uint2* __restrict__ K,
    const uint2* __restrict__ V, const int* __restrict__ lens,
    uint32_t* __restrict__ Out)
{
    extern __shared__ uint2 smu2[];
    uint2*    Ksm = smu2;
    uint2*    Vsm = smu2 + FA_K_U2;
    uint32_t* Ps  = (uint32_t*)(smu2 + FA_K_U2 + FA_V_U2);

    const int qt = (int)(gridDim.x - 1 - blockIdx.x);
    const int bh = blockIdx.y;
    const int b  = bh >> 4;
    const int h  = bh & 15;
    const float* Qg = Q + ((size_t)bh * S_LEN + qt * 64) * HD;
    const uint2* Kg = K + (size_t)bh * S_LEN * 32;
    const uint2* Vg = V + (size_t)bh * 64 * VP;
    const int klen = lens[b];

    const int tid = threadIdx.x;
    const int wq = tid >> 5;
    const int lane = tid & 31;
    const int lr = lane >> 2;
    const int lc = lane & 3;
    const int r0 = wq * 16 + lr;

    const int nt = min(qt + 1, (klen + 63) >> 6);

    auto issue_K = [&](int st, int t) {
#pragma unroll
        for (int i = 0; i < 8; i++) {
            int cid = tid + i * 128;
            int row = cid >> 4;
            int ch  = (cid & 15) * 2;
            cpa16(&Ksm[st * 64 * FSK2 + row * FSK2 + ch],
                  &Kg[(size_t)(t * 64 + row) * 32 + ch]);
        }
    };
    auto issue_V = [&](int t) {
#pragma unroll
        for (int i = 0; i < 8; i++) {
            int cid = tid + i * 128;
            int row = cid >> 4;
            int ch  = (cid & 15) * 2;
            cpa16(&Vsm[row * FSV2 + ch],
                  &Vg[(size_t)row * VP + t * 32 + ch]);
        }
    };

    issue_K(0, 0);
    CPA_COMMIT();

    float* Qstage = (float*)Ps;
    for (int idx = tid; idx < 64 * 16; idx += 128) {
        int q = idx >> 4, d0 = (idx & 15) << 2;
        float4 v = *(const float4*)&Qg[q * HD + d0];
        Qstage[q * 68 + d0 + 0] = v.x;
        Qstage[q * 68 + d0 + 1] = v.y;
        Qstage[q * 68 + d0 + 2] = v.z;
        Qstage[q * 68 + d0 + 3] = v.w;
    }
    __syncthreads();

    uint32_t qh[8][4], ql[8][4];
#pragma unroll
    for (int kb = 0; kb < 8; kb++) {
        float f[4];
        f[0] = Qstage[(r0    ) * 68 + kb * 8 + lc    ];
        f[1] = Qstage[(r0 + 8) * 68 + kb * 8 + lc    ];
        f[2] = Qstage[(r0    ) * 68 + kb * 8 + lc + 4];
        f[3] = Qstage[(r0 + 8) * 68 + kb * 8 + lc + 4];
#pragma unroll
        for (int i = 0; i < 4; i++) {
            qh[kb][i] = f2tf32(f[i]);
            ql[kb][i] = f2tf32(f[i] - __uint_as_float(qh[kb][i]));
        }
    }
    __syncthreads();

    float oacc[8][4];
#pragma unroll
    for (int nf = 0; nf < 8; nf++)
#pragma unroll
        for (int i = 0; i < 4; i++) oacc[nf][i] = 0.f;
    float mrow0 = -1e30f, mrow1 = -1e30f;
    float lrow0 = 0.f, lrow1 = 0.f;

    const int qg0 = qt * 64 + r0;

    for (int t = 0; t < nt; t++) {
        const int st = t & 1;
        issue_V(t);
        CPA_COMMIT();
        if (t + 1 < nt) issue_K(st ^ 1, t + 1);
        CPA_COMMIT();
        CPA_WAIT2();
        __syncthreads();

        const uint2* Kt = Ksm + st * 64 * FSK2;

        float sf[8][4];
#pragma unroll
        for (int nf = 0; nf < 8; nf++)
#pragma unroll
            for (int i = 0; i < 4; i++) sf[nf][i] = 0.f;

#pragma unroll
        for (int kb = 0; kb < 8; kb++) {
            uint2 kk[8];
#pragma unroll
            for (int nf = 0; nf < 8; nf++)
                kk[nf] = Kt[(nf * 8 + lr) * FSK2 + kb * 4 + lc];
#pragma unroll
            for (int nf = 0; nf < 8; nf++)
                MMA_TF32(sf[nf], qh[kb], kk[nf].x, kk[nf].y);
#pragma unroll
            for (int nf = 0; nf < 8; nf++)
                MMA_TF32(sf[nf], ql[kb], kk[nf].x, kk[nf].y);
        }

        const bool edge = (t == qt) || ((t + 1) * 64 > klen);
#pragma unroll
        for (int nf = 0; nf < 8; nf++) {
            if (edge) {
                int kg = t * 64 + nf * 8 + lc * 2;
                sf[nf][0] = (kg     <= qg0     && kg     < klen) ? sf[nf][0] * 0.125f : -1e30f;
                sf[nf][1] = (kg + 1 <= qg0     && kg + 1 < klen) ? sf[nf][1] * 0.125f : -1e30f;
                sf[nf][2] = (kg     <= qg0 + 8 && kg     < klen) ? sf[nf][2] * 0.125f : -1e30f;
                sf[nf][3] = (kg + 1 <= qg0 + 8 && kg + 1 < klen) ? sf[nf][3] * 0.125f : -1e30f;
            } else {
                sf[nf][0] *= 0.125f; sf[nf][1] *= 0.125f;
                sf[nf][2] *= 0.125f; sf[nf][3] *= 0.125f;
            }
        }

        float m0 = -1e30f, m1 = -1e30f;
#pragma unroll
        for (int nf = 0; nf < 8; nf++) {
            m0 = fmaxf(m0, fmaxf(sf[nf][0], sf[nf][1]));
            m1 = fmaxf(m1, fmaxf(sf[nf][2], sf[nf][3]));
        }
        m0 = fmaxf(m0, __shfl_xor_sync(0xffffffffu, m0, 1));
        m0 = fmaxf(m0, __shfl_xor_sync(0xffffffffu, m0, 2));
        m1 = fmaxf(m1, __shfl_xor_sync(0xffffffffu, m1, 1));
        m1 = fmaxf(m1, __shfl_xor_sync(0xffffffffu, m1, 2));

        float mn0 = fmaxf(mrow0, m0), mn1 = fmaxf(mrow1, m1);
        float al0 = __expf(mrow0 - mn0), al1 = __expf(mrow1 - mn1);
        mrow0 = mn0; mrow1 = mn1;

        float s0 = 0.f, s1 = 0.f;
#pragma unroll
        for (int nf = 0; nf < 8; nf++) {
            float p0 = __expf(sf[nf][0] - mn0);
            float p1 = __expf(sf[nf][1] - mn0);
            float p2 = __expf(sf[nf][2] - mn1);
            float p3 = __expf(sf[nf][3] - mn1);
            sf[nf][0] = p0; sf[nf][1] = p1; sf[nf][2] = p2; sf[nf][3] = p3;
            s0 += p0 + p1; s1 += p2 + p3;
        }
        s0 += __shfl_xor_sync(0xffffffffu, s0, 1);
        s0 += __shfl_xor_sync(0xffffffffu, s0, 2);
        s1 += __shfl_xor_sync(0xffffffffu, s1, 1);
        s1 += __shfl_xor_sync(0xffffffffu, s1, 2);
        lrow0 = lrow0 * al0 + s0;
        lrow1 = lrow1 * al1 + s1;

#pragma unroll
        for (int nf = 0; nf < 8; nf++) {
            oacc[nf][0] *= al0; oacc[nf][1] *= al0;
            oacc[nf][2] *= al1; oacc[nf][3] *= al1;
        }

        uint32_t* PsW = Ps + wq * 16 * FS_PS;
#pragma unroll
        for (int nf = 0; nf < 8; nf++) {
            int j0 = lc * 2;
            int s0i = 2 * (j0 & 3) + (j0 >> 2);
            int j1 = j0 + 1;
            int s1i = 2 * (j1 & 3) + (j1 >> 2);
            int base = nf * 8;
            PsW[ lr      * FS_PS + base + s0i] = f2tf32(sf[nf][0]);
            PsW[ lr      * FS_PS + base + s1i] = f2tf32(sf[nf][1]);
            PsW[(lr + 8) * FS_PS + base + s0i] = f2tf32(sf[nf][2]);
            PsW[(lr + 8) * FS_PS + base + s1i] = f2tf32(sf[nf][3]);
        }
        __syncwarp();

        CPA_WAIT1();
        __syncthreads();

#pragma unroll
        for (int kb = 0; kb < 8; kb++) {
            uint32_t af[4];
            {
                uint2 x = *(const uint2*)&PsW[ lr      * FS_PS + kb * 8 + lc * 2];
                uint2 y = *(const uint2*)&PsW[(lr + 8) * FS_PS + kb * 8 + lc * 2];
                af[0] = x.x; af[1] = y.x; af[2] = x.y; af[3] = y.y;
            }
#pragma unroll
            for (int nf = 0; nf < 8; nf++) {
                int n0 = nf * 8 + lr;
                uint2 vv = Vsm[n0 * FSV2 + kb * 4 + lc];
                MMA_TF32(oacc[nf], af, vv.x, vv.y);
            }
        }
        __syncthreads();
    }

    const int pos0 = ((lc & 1) << 2) + (lc >> 1);
    float inv0 = 1.0f / lrow0, inv1 = 1.0f / lrow1;
#pragma unroll
    for (int nf = 0; nf < 8; nf++) {
        int base = h * HD + nf * 8;
        size_t ro0 = ((size_t)(b * S_LEN + qg0    )) * DM + base;
        size_t ro1 = ((size_t)(b * S_LEN + qg0 + 8)) * DM + base;
        Out[ro0 + pos0    ] = f2tf32(oacc[nf][0] * inv0);
        Out[ro0 + pos0 + 2] = f2tf32(oacc[nf][1] * inv0);
        Out[ro1 + pos0    ] = f2tf32(oacc[nf][2] * inv1);
        Out[ro1 + pos0 + 2] = f2tf32(oacc[nf][3] * inv1);
    }
}

// ============================================================
extern "C" void kernel_launch(void* const* d_in, const int* in_sizes, int n_in,
                              void* d_out, int out_size)
{
    const float* hidden = (const float*)d_in[0];
    const float* w_qkv  = (const float*)d_in[1];
    const float* w_out  = (const float*)d_in[2];
    const void*  attn_mask = d_in[3];
    // d_in[4] = causal_mask (implicit)
    const int* pos_xyz = (const int*)d_in[5];
    float* out = (float*)d_out;

    uint32_t *hidp, *wqkvp, *woutp, *ks, *vt, *ao;
    float *q, *part;
    int* lens;
    cudaGetSymbolAddress((void**)&hidp,  g_hid_p);
    cudaGetSymbolAddress((void**)&wqkvp, g_wqkv_p);
    cudaGetSymbolAddress((void**)&woutp, g_wout_p);
    cudaGetSymbolAddress((void**)&q,     g_q);
    cudaGetSymbolAddress((void**)&ks,    g_ks);
    cudaGetSymbolAddress((void**)&vt,    g_vt);
    cudaGetSymbolAddress((void**)&ao,    g_ao);
    cudaGetSymbolAddress((void**)&part,  g_part);
    cudaGetSymbolAddress((void**)&lens,  g_len);
    float* p0 = part;
    float* p1 = part + (size_t)M_TOK * DM;

    compute_lens<<<BB, 256>>>(attn_mask);

    // 0. Pre-convert all GEMM operands (single kernel)
    {
        int ntot = CVT_N1 + CVT_N2 + CVT_N3;
        cvt_pair_all<<<(ntot + 255) / 256, 256>>>(hidden, w_qkv, w_out,
                                                  hidp, wqkvp, woutp);
    }

    // 1. QKV projection + fused RoPE/scatter (BK=64)
    {
        dim3 grid(3 * DM / 64, M_TOK / 128);
        gemm_qkv_rope<<<grid, 128>>>(hidp, wqkvp, pos_xyz, q, ks, vt);
    }

    // 2. Flash attention
    {
        cudaFuncSetAttribute(flash_attn_tf32,
                             cudaFuncAttributeMaxDynamicSharedMemorySize,
                             FA_SMEM_BYTES);
        dim3 grid(S_LEN / 64, BB * NH);
        flash_attn_tf32<<<grid, 128, FA_SMEM_BYTES>>>(
            q, (const uint2*)ks, (const uint2*)vt, lens, ao);
    }

    // 3. Output projection (BK=64, K-split x2) + add
    {
        dim3 grid(DM / 64, M_TOK / 128, 2);
        gemm_out_ksplit<<<grid, 128>>>(ao, woutp, p0, p1, DM, DM);
        int n4 = M_TOK * DM / 4;
        add_out<<<(n4 + 255) / 256, 256>>>(p0, p1, out, n4);
    }
}

// round 17
// speedup vs baseline: 1.0526x; 1.0526x over previous
#include <cuda_runtime.h>
#include <math.h>
#include <stdint.h>

#define S_LEN 2048
#define NH 16
#define HD 64
#define DM 1024
#define BB 2
#define M_TOK (BB * S_LEN)   // 4096
#define VP (S_LEN / 2)       // uint2 per V d-row

// -------- scratch (static device globals; allocation-free) --------
__device__ uint32_t g_hid_p[(size_t)M_TOK * DM];     // hidden, tf32 paired
__device__ uint32_t g_wqkv_p[(size_t)3 * DM * DM];   // w_qkv, tf32 paired
__device__ uint32_t g_wout_p[(size_t)DM * DM];       // w_out, tf32 paired
__device__ float    g_q [(size_t)M_TOK * DM];        // [B,H,S,Dh] f32
__device__ uint32_t g_ks[(size_t)M_TOK * DM];        // K tf32 hi, d-paired rows
__device__ uint32_t g_vt[(size_t)M_TOK * DM];        // V^T tf32, key-paired
__device__ uint32_t g_ao[(size_t)M_TOK * DM];        // attn out, tf32 paired
__device__ int      g_len[BB];

__device__ __forceinline__ uint32_t f2tf32(float f) {
    uint32_t r;
    asm("cvt.rna.tf32.f32 %0, %1;" : "=r"(r) : "f"(f));
    return r;
}

#define MMA_TF32(c, a, b0, b1)                                              \
    asm volatile(                                                           \
        "mma.sync.aligned.m16n8k8.row.col.f32.tf32.tf32.f32 "               \
        "{%0,%1,%2,%3}, {%4,%5,%6,%7}, {%8,%9}, {%0,%1,%2,%3};"             \
        : "+f"((c)[0]), "+f"((c)[1]), "+f"((c)[2]), "+f"((c)[3])            \
        : "r"((a)[0]), "r"((a)[1]), "r"((a)[2]), "r"((a)[3]),               \
          "r"(b0), "r"(b1))

__device__ __forceinline__ void cpa16(void* smem, const void* gmem) {
    uint32_t s = (uint32_t)__cvta_generic_to_shared(smem);
    asm volatile("cp.async.cg.shared.global [%0], [%1], 16;" :: "r"(s), "l"(gmem));
}
#define CPA_COMMIT() asm volatile("cp.async.commit_group;")
#define CPA_WAIT1()  asm volatile("cp.async.wait_group 1;")
#define CPA_WAIT2()  asm volatile("cp.async.wait_group 2;")

// ============================================================
// Mask length extraction — dtype-agnostic (prefix-true mask).
// ============================================================
__global__ void compute_lens(const void* __restrict__ mask)
{
    __shared__ int cnt;
    const int b = blockIdx.x;
    if (threadIdx.x == 0) cnt = 0;
    __syncthreads();

    const unsigned char* bytes = (const unsigned char*)mask;
    int dtype;
    if (*(const float*)mask == 1.0f) dtype = 2;
    else if (bytes[0] == 1 && bytes[1] == 0) dtype = 1;
    else dtype = 0;

    int local = 0;
    for (int s = threadIdx.x; s < S_LEN; s += blockDim.x) {
        int v;
        if (dtype == 2)      v = (((const float*)mask)[b * S_LEN + s] != 0.0f);
        else if (dtype == 1) v = (((const int*)mask)[b * S_LEN + s] != 0);
        else                 v = (bytes[b * S_LEN + s] != 0);
        local += v;
    }
    atomicAdd(&cnt, local);
    __syncthreads();
    if (threadIdx.x == 0) g_len[b] = cnt;
}

// ============================================================
// Single fused converter: f32 -> paired tf32 for all 3 operands.
// ============================================================
#define CVT_N1 (M_TOK * DM)
#define CVT_N2 (3 * DM * DM)
#define CVT_N3 (DM * DM)

__global__ void cvt_pair_all(const float* __restrict__ h,
                             const float* __restrict__ wq,
                             const float* __restrict__ wo,
                             uint32_t* __restrict__ hp,
                             uint32_t* __restrict__ wqp,
                             uint32_t* __restrict__ wop)
{
    int idx = blockIdx.x * blockDim.x + threadIdx.x;
    const float* in; uint32_t* out; int i;
    if (idx < CVT_N1)                 { in = h;  out = hp;  i = idx; }
    else if (idx < CVT_N1 + CVT_N2)   { in = wq; out = wqp; i = idx - CVT_N1; }
    else if (idx < CVT_N1 + CVT_N2 + CVT_N3)
                                      { in = wo; out = wop; i = idx - CVT_N1 - CVT_N2; }
    else return;
    int blk = i >> 3, p = i & 7;
    int c = (p & 1) ? ((p >> 1) + 4) : (p >> 1);
    out[i] = f2tf32(in[(size_t)blk * 8 + c]);
}

// ============================================================
// Paired-tf32 GEMM body (128x64 block, 128 thr, 2-stage, BK=32,
// 3 CTAs/SM — the R13-proven configuration).
// ============================================================
#define GSP 20   // uint2 per smem row

struct GemmCtx {
    float c[4][4][4];
    int bm, bn, wm, wn, lr, lc;
};

template <typename EPI>
__device__ __forceinline__ void gemm_tf32p_body(
    const uint32_t* __restrict__ A, const uint32_t* __restrict__ B,
    int K, uint2* As, uint2* Bs, EPI epi)
{
    const int bm = blockIdx.y * 128;
    const int bn = blockIdx.x * 64;
    const int tid = threadIdx.x;
    const int wid = tid >> 5;
    const int lane = tid & 31;
    const int wm = (wid & 1) * 64;
    const int wn = (wid >> 1) * 32;
    const int lr = lane >> 2;
    const int lc = lane & 3;

    GemmCtx g;
    g.bm = bm; g.bn = bn; g.wm = wm; g.wn = wn; g.lr = lr; g.lc = lc;
#pragma unroll
    for (int i = 0; i < 4; i++)
#pragma unroll
        for (int j = 0; j < 4; j++)
#pragma unroll
            for (int r = 0; r < 4; r++) g.c[i][j][r] = 0.f;

    auto issue = [&](int st, int k0 /*u32 units*/) {
#pragma unroll
        for (int i = 0; i < 8; i++) {
            int cid = tid + i * 128;
            int row = cid >> 3;
            int cc  = (cid & 7) * 2;
            cpa16(&As[st * 128 * GSP + row * GSP + cc],
                  &A[(size_t)(bm + row) * K + k0 + cc * 2]);
        }
#pragma unroll
        for (int i = 0; i < 4; i++) {
            int cid = tid + i * 128;
            int row = cid >> 3;
            int cc  = (cid & 7) * 2;
            cpa16(&Bs[st * 64 * GSP + row * GSP + cc],
                  &B[(size_t)(bn + row) * K + k0 + cc * 2]);
        }
        CPA_COMMIT();
    };

    const int nIt = K / 32;
    issue(0, 0);

    for (int it = 0; it < nIt; it++) {
        const int st = it & 1;
        if (it + 1 < nIt) issue(st ^ 1, (it + 1) * 32);
        else CPA_COMMIT();
        CPA_WAIT1();
        __syncthreads();

        const uint2* Asb = As + st * 128 * GSP;
        const uint2* Bsb = Bs + st * 64 * GSP;
#pragma unroll
        for (int ks = 0; ks < 4; ks++) {
            uint32_t af[4][4], bf[4][2];
#pragma unroll
            for (int mf = 0; mf < 4; mf++) {
                int r0 = wm + mf * 16 + lr;
                uint2 x = Asb[(r0    ) * GSP + ks * 4 + lc];
                uint2 y = Asb[(r0 + 8) * GSP + ks * 4 + lc];
                af[mf][0] = x.x; af[mf][1] = y.x;
                af[mf][2] = x.y; af[mf][3] = y.y;
            }
#pragma unroll
            for (int nf = 0; nf < 4; nf++) {
                uint2 z = Bsb[(wn + nf * 8 + lr) * GSP + ks * 4 + lc];
                bf[nf][0] = z.x; bf[nf][1] = z.y;
            }
#pragma unroll
            for (int mf = 0; mf < 4; mf++)
#pragma unroll
                for (int nf = 0; nf < 4; nf++)
                    MMA_TF32(g.c[mf][nf], af[mf], bf[nf][0], bf[nf][1]);
        }
        __syncthreads();
    }
    epi(g);
}

#define GEMM_SMEM_A (2 * 128 * GSP)
#define GEMM_SMEM_B (2 * 64 * GSP)

// ---- out-projection (plain, R13 config) ----
__global__ __launch_bounds__(128, 3) void gemm_out(
    const uint32_t* __restrict__ A, const uint32_t* __restrict__ B,
    float* __restrict__ C, int N, int K)
{
    __shared__ uint2 As[GEMM_SMEM_A];
    __shared__ uint2 Bs[GEMM_SMEM_B];
    gemm_tf32p_body(A, B, K, As, Bs, [&](GemmCtx& g) {
#pragma unroll
        for (int mf = 0; mf < 4; mf++)
#pragma unroll
            for (int nf = 0; nf < 4; nf++) {
                int row = g.bm + g.wm + mf * 16 + g.lr;
                int col = g.bn + g.wn + nf * 8 + g.lc * 2;
                *(float2*)&C[(size_t)row * N + col] =
                    make_float2(g.c[mf][nf][0], g.c[mf][nf][1]);
                *(float2*)&C[(size_t)(row + 8) * N + col] =
                    make_float2(g.c[mf][nf][2], g.c[mf][nf][3]);
            }
    });
}

// ---- QKV GEMM with fused RoPE epilogue.
// V (p==2) tiles: stage 128x64 accums in smem (aliasing As), then
// coalesced transposed write in the key-paired V^T layout. ----
__global__ __launch_bounds__(128, 3) void gemm_qkv_rope(
    const uint32_t* __restrict__ A, const uint32_t* __restrict__ B,
    const int* __restrict__ pos_xyz,
    float* __restrict__ Q, uint32_t* __restrict__ Ks,
    uint32_t* __restrict__ Vt)
{
    __shared__ uint2 As[GEMM_SMEM_A];
    __shared__ uint2 Bs[GEMM_SMEM_B];
    gemm_tf32p_body(A, B, DM, As, Bs, [&](GemmCtx& g) {
        const int tid = threadIdx.x;
        const int p = g.bn >> 10;
        const int rem = g.bn & 1023;
        const int hh = rem >> 6;

        if (p == 2) {
            // ---- V tile: stage to smem [128 rows][68] f32 ----
            float* Vstage = (float*)As;       // 128*68*4 = 34.8KB <= As+Bs
#pragma unroll
            for (int mf = 0; mf < 4; mf++)
#pragma unroll
                for (int rr = 0; rr < 2; rr++) {
                    int ml = g.wm + mf * 16 + g.lr + rr * 8;
#pragma unroll
                    for (int nf = 0; nf < 4; nf++) {
                        int dl = g.wn + nf * 8 + g.lc * 2;
                        Vstage[ml * 68 + dl    ] = g.c[mf][nf][rr * 2];
                        Vstage[ml * 68 + dl + 1] = g.c[mf][nf][rr * 2 + 1];
                    }
                }
            __syncthreads();

            // coalesced transposed write: warp w -> d rows [w*16, w*16+16),
            // lanes span keys (lane l -> keys 4l..4l+3 within 128-token tile).
            const int wid = tid >> 5, lane = tid & 31;
            const int m0 = g.bm;               // 128 consecutive tokens, same b
            const int b  = m0 >> 11;
            const int s0 = m0 & (S_LEN - 1);
            const int bh = b * NH + hh;
#pragma unroll
            for (int dd = 0; dd < 16; dd++) {
                int d = wid * 16 + dd;
                size_t row = (size_t)bh * 64 + d;
                // lane covers u32 idx [lane*4, lane*4+4) of the 128-key span
                uint32_t v4[4];
#pragma unroll
                for (int e = 0; e < 4; e++) {
                    int i = (lane * 4 + e) & 7;        // idx within 8-block
                    int blk8 = (lane * 4 + e) >> 3;
                    int key = blk8 * 8 + (i >> 1) + ((i & 1) << 2);
                    v4[e] = f2tf32(Vstage[key * 68 + d]);
                }
                *(uint4*)&Vt[row * S_LEN + s0 + lane * 4] =
                    make_uint4(v4[0], v4[1], v4[2], v4[3]);
            }
        } else {
            int   dP[4], axP[4];
            float invP[4];
#pragma unroll
            for (int nf = 0; nf < 4; nf++) {
                int d = (g.bn + g.wn + nf * 8 + g.lc * 2) & 63;
                dP[nf] = d;
                int axis, dim, dd;
                if (d < 20)      { axis = 0; dim = 20; dd = d; }
                else if (d < 40) { axis = 1; dim = 20; dd = d - 20; }
                else             { axis = 2; dim = 24; dd = d - 40; }
                axP[nf] = axis;
                invP[nf] = exp2f(-13.287712379549449f * (float)dd / (float)dim);
            }
#pragma unroll
            for (int mf = 0; mf < 4; mf++) {
#pragma unroll
                for (int rr = 0; rr < 2; rr++) {
                    int m = g.bm + g.wm + mf * 16 + g.lr + rr * 8;
                    int b = m >> 11, s = m & (S_LEN - 1);
                    int bh = b * NH + hh;
#pragma unroll
                    for (int nf = 0; nf < 4; nf++) {
                        float c0 = g.c[mf][nf][rr * 2];
                        float c1 = g.c[mf][nf][rr * 2 + 1];
                        int d = dP[nf];
                        float pos = (float)pos_xyz[m * 3 + axP[nf]];
                        float sn, cs;
                        sincosf(pos * invP[nf], &sn, &cs);
                        float o0 = c0 * cs - c1 * sn;
                        float o1 = c1 * cs + c0 * sn;
                        if (p == 0) {
                            size_t o = ((size_t)bh * S_LEN + s) * HD + d;
                            Q[o] = o0; Q[o + 1] = o1;
                        } else {
                            size_t rowb = ((size_t)bh * S_LEN + s) * HD;
                            int j = d & 7, blk = d >> 3;
                            Ks[rowb + blk * 8 + 2 * (j & 3)  + (j >> 2)]  = f2tf32(o0);
                            int j1 = j + 1;
                            Ks[rowb + blk * 8 + 2 * (j1 & 3) + (j1 >> 2)] = f2tf32(o1);
                        }
                    }
                }
            }
        }
    });
}

// ============================================================
// Flash attention (R15/R16 — best measured, 196.6 us).
// ============================================================
#define FSK2 36
#define FSV2 36
#define FS_PS 76
#define FA_K_U2   (2 * 64 * FSK2)
#define FA_V_U2   (64 * FSV2)
#define FA_PS_U32 (4 * 16 * FS_PS)
#define FA_SMEM_BYTES ((FA_K_U2 + FA_V_U2) * 8 + FA_PS_U32 * 4)

__global__ __launch_bounds__(128, 3) void flash_attn_tf32(
    const float* __restrict__ Q, const uint2* __restrict__ K,
    const uint2* __restrict__ V, const int* __restrict__ lens,
    uint32_t* __restrict__ Out)
{
    extern __shared__ uint2 smu2[];
    uint2*    Ksm = smu2;
    uint2*    Vsm = smu2 + FA_K_U2;
    uint32_t* Ps  = (uint32_t*)(smu2 + FA_K_U2 + FA_V_U2);

    const int qt = (int)(gridDim.x - 1 - blockIdx.x);
    const int bh = blockIdx.y;
    const int b  = bh >> 4;
    const int h  = bh & 15;
    const float* Qg = Q + ((size_t)bh * S_LEN + qt * 64) * HD;
    const uint2* Kg = K + (size_t)bh * S_LEN * 32;
    const uint2* Vg = V + (size_t)bh * 64 * VP;
    const int klen = lens[b];

    const int tid = threadIdx.x;
    const int wq = tid >> 5;
    const int lane = tid & 31;
    const int lr = lane >> 2;
    const int lc = lane & 3;
    const int r0 = wq * 16 + lr;

    const int nt = min(qt + 1, (klen + 63) >> 6);

    auto issue_K = [&](int st, int t) {
#pragma unroll
        for (int i = 0; i < 8; i++) {
            int cid = tid + i * 128;
            int row = cid >> 4;
            int ch  = (cid & 15) * 2;
            cpa16(&Ksm[st * 64 * FSK2 + row * FSK2 + ch],
                  &Kg[(size_t)(t * 64 + row) * 32 + ch]);
        }
    };
    auto issue_V = [&](int t) {
#pragma unroll
        for (int i = 0; i < 8; i++) {
            int cid = tid + i * 128;
            int row = cid >> 4;
            int ch  = (cid & 15) * 2;
            cpa16(&Vsm[row * FSV2 + ch],
                  &Vg[(size_t)row * VP + t * 32 + ch]);
        }
    };

    issue_K(0, 0);
    CPA_COMMIT();

    float* Qstage = (float*)Ps;
    for (int idx = tid; idx < 64 * 16; idx += 128) {
        int q = idx >> 4, d0 = (idx & 15) << 2;
        float4 v = *(const float4*)&Qg[q * HD + d0];
        Qstage[q * 68 + d0 + 0] = v.x;
        Qstage[q * 68 + d0 + 1] = v.y;
        Qstage[q * 68 + d0 + 2] = v.z;
        Qstage[q * 68 + d0 + 3] = v.w;
    }
    __syncthreads();

    uint32_t qh[8][4], ql[8][4];
#pragma unroll
    for (int kb = 0; kb < 8; kb++) {
        float f[4];
        f[0] = Qstage[(r0    ) * 68 + kb * 8 + lc    ];
        f[1] = Qstage[(r0 + 8) * 68 + kb * 8 + lc    ];
        f[2] = Qstage[(r0    ) * 68 + kb * 8 + lc + 4];
        f[3] = Qstage[(r0 + 8) * 68 + kb * 8 + lc + 4];
#pragma unroll
        for (int i = 0; i < 4; i++) {
            qh[kb][i] = f2tf32(f[i]);
            ql[kb][i] = f2tf32(f[i] - __uint_as_float(qh[kb][i]));
        }
    }
    __syncthreads();

    float oacc[8][4];
#pragma unroll
    for (int nf = 0; nf < 8; nf++)
#pragma unroll
        for (int i = 0; i < 4; i++) oacc[nf][i] = 0.f;
    float mrow0 = -1e30f, mrow1 = -1e30f;
    float lrow0 = 0.f, lrow1 = 0.f;

    const int qg0 = qt * 64 + r0;

    for (int t = 0; t < nt; t++) {
        const int st = t & 1;
        issue_V(t);
        CPA_COMMIT();
        if (t + 1 < nt) issue_K(st ^ 1, t + 1);
        CPA_COMMIT();
        CPA_WAIT2();
        __syncthreads();

        const uint2* Kt = Ksm + st * 64 * FSK2;

        float sf[8][4];
#pragma unroll
        for (int nf = 0; nf < 8; nf++)
#pragma unroll
            for (int i = 0; i < 4; i++) sf[nf][i] = 0.f;

#pragma unroll
        for (int kb = 0; kb < 8; kb++) {
            uint2 kk[8];
#pragma unroll
            for (int nf = 0; nf < 8; nf++)
                kk[nf] = Kt[(nf * 8 + lr) * FSK2 + kb * 4 + lc];
#pragma unroll
            for (int nf = 0; nf < 8; nf++)
                MMA_TF32(sf[nf], qh[kb], kk[nf].x, kk[nf].y);
#pragma unroll
            for (int nf = 0; nf < 8; nf++)
                MMA_TF32(sf[nf], ql[kb], kk[nf].x, kk[nf].y);
        }

        const bool edge = (t == qt) || ((t + 1) * 64 > klen);
#pragma unroll
        for (int nf = 0; nf < 8; nf++) {
            if (edge) {
                int kg = t * 64 + nf * 8 + lc * 2;
                sf[nf][0] = (kg     <= qg0     && kg     < klen) ? sf[nf][0] * 0.125f : -1e30f;
                sf[nf][1] = (kg + 1 <= qg0     && kg + 1 < klen) ? sf[nf][1] * 0.125f : -1e30f;
                sf[nf][2] = (kg     <= qg0 + 8 && kg     < klen) ? sf[nf][2] * 0.125f : -1e30f;
                sf[nf][3] = (kg + 1 <= qg0 + 8 && kg + 1 < klen) ? sf[nf][3] * 0.125f : -1e30f;
            } else {
                sf[nf][0] *= 0.125f; sf[nf][1] *= 0.125f;
                sf[nf][2] *= 0.125f; sf[nf][3] *= 0.125f;
            }
        }

        float m0 = -1e30f, m1 = -1e30f;
#pragma unroll
        for (int nf = 0; nf < 8; nf++) {
            m0 = fmaxf(m0, fmaxf(sf[nf][0], sf[nf][1]));
            m1 = fmaxf(m1, fmaxf(sf[nf][2], sf[nf][3]));
        }
        m0 = fmaxf(m0, __shfl_xor_sync(0xffffffffu, m0, 1));
        m0 = fmaxf(m0, __shfl_xor_sync(0xffffffffu, m0, 2));
        m1 = fmaxf(m1, __shfl_xor_sync(0xffffffffu, m1, 1));
        m1 = fmaxf(m1, __shfl_xor_sync(0xffffffffu, m1, 2));

        float mn0 = fmaxf(mrow0, m0), mn1 = fmaxf(mrow1, m1);
        float al0 = __expf(mrow0 - mn0), al1 = __expf(mrow1 - mn1);
        mrow0 = mn0; mrow1 = mn1;

        float s0 = 0.f, s1 = 0.f;
#pragma unroll
        for (int nf = 0; nf < 8; nf++) {
            float p0 = __expf(sf[nf][0] - mn0);
            float p1 = __expf(sf[nf][1] - mn0);
            float p2 = __expf(sf[nf][2] - mn1);
            float p3 = __expf(sf[nf][3] - mn1);
            sf[nf][0] = p0; sf[nf][1] = p1; sf[nf][2] = p2; sf[nf][3] = p3;
            s0 += p0 + p1; s1 += p2 + p3;
        }
        s0 += __shfl_xor_sync(0xffffffffu, s0, 1);
        s0 += __shfl_xor_sync(0xffffffffu, s0, 2);
        s1 += __shfl_xor_sync(0xffffffffu, s1, 1);
        s1 += __shfl_xor_sync(0xffffffffu, s1, 2);
        lrow0 = lrow0 * al0 + s0;
        lrow1 = lrow1 * al1 + s1;

#pragma unroll
        for (int nf = 0; nf < 8; nf++) {
            oacc[nf][0] *= al0; oacc[nf][1] *= al0;
            oacc[nf][2] *= al1; oacc[nf][3] *= al1;
        }

        uint32_t* PsW = Ps + wq * 16 * FS_PS;
#pragma unroll
        for (int nf = 0; nf < 8; nf++) {
            int j0 = lc * 2;
            int s0i = 2 * (j0 & 3) + (j0 >> 2);
            int j1 = j0 + 1;
            int s1i = 2 * (j1 & 3) + (j1 >> 2);
            int base = nf * 8;
            PsW[ lr      * FS_PS + base + s0i] = f2tf32(sf[nf][0]);
            PsW[ lr      * FS_PS + base + s1i] = f2tf32(sf[nf][1]);
            PsW[(lr + 8) * FS_PS + base + s0i] = f2tf32(sf[nf][2]);
            PsW[(lr + 8) * FS_PS + base + s1i] = f2tf32(sf[nf][3]);
        }
        __syncwarp();

        CPA_WAIT1();
        __syncthreads();

#pragma unroll
        for (int kb = 0; kb < 8; kb++) {
            uint32_t af[4];
            {
                uint2 x = *(const uint2*)&PsW[ lr      * FS_PS + kb * 8 + lc * 2];
                uint2 y = *(const uint2*)&PsW[(lr + 8) * FS_PS + kb * 8 + lc * 2];
                af[0] = x.x; af[1] = y.x; af[2] = x.y; af[3] = y.y;
            }
#pragma unroll
            for (int nf = 0; nf < 8; nf++) {
                int n0 = nf * 8 + lr;
                uint2 vv = Vsm[n0 * FSV2 + kb * 4 + lc];
                MMA_TF32(oacc[nf], af, vv.x, vv.y);
            }
        }
        __syncthreads();
    }

    const int pos0 = ((lc & 1) << 2) + (lc >> 1);
    float inv0 = 1.0f / lrow0, inv1 = 1.0f / lrow1;
#pragma unroll
    for (int nf = 0; nf < 8; nf++) {
        int base = h * HD + nf * 8;
        size_t ro0 = ((size_t)(b * S_LEN + qg0    )) * DM + base;
        size_t ro1 = ((size_t)(b * S_LEN + qg0 + 8)) * DM + base;
        Out[ro0 + pos0    ] = f2tf32(oacc[nf][0] * inv0);
        Out[ro0 + pos0 + 2] = f2tf32(oacc[nf][1] * inv0);
        Out[ro1 + pos0    ] = f2tf32(oacc[nf][2] * inv1);
        Out[ro1 + pos0 + 2] = f2tf32(oacc[nf][3] * inv1);
    }
}

// ============================================================
extern "C" void kernel_launch(void* const* d_in, const int* in_sizes, int n_in,
                              void* d_out, int out_size)
{
    const float* hidden = (const float*)d_in[0];
    const float* w_qkv  = (const float*)d_in[1];
    const float* w_out  = (const float*)d_in[2];
    const void*  attn_mask = d_in[3];
    // d_in[4] = causal_mask (implicit)
    const int* pos_xyz = (const int*)d_in[5];
    float* out = (float*)d_out;

    uint32_t *hidp, *wqkvp, *woutp, *ks, *vt, *ao;
    float *q;
    int* lens;
    cudaGetSymbolAddress((void**)&hidp,  g_hid_p);
    cudaGetSymbolAddress((void**)&wqkvp, g_wqkv_p);
    cudaGetSymbolAddress((void**)&woutp, g_wout_p);
    cudaGetSymbolAddress((void**)&q,     g_q);
    cudaGetSymbolAddress((void**)&ks,    g_ks);
    cudaGetSymbolAddress((void**)&vt,    g_vt);
    cudaGetSymbolAddress((void**)&ao,    g_ao);
    cudaGetSymbolAddress((void**)&lens,  g_len);

    compute_lens<<<BB, 256>>>(attn_mask);

    // 0. Pre-convert all GEMM operands (single kernel)
    {
        int ntot = CVT_N1 + CVT_N2 + CVT_N3;
        cvt_pair_all<<<(ntot + 255) / 256, 256>>>(hidden, w_qkv, w_out,
                                                  hidp, wqkvp, woutp);
    }

    // 1. QKV projection + fused RoPE/scatter (coalesced V^T epilogue)
    {
        dim3 grid(3 * DM / 64, M_TOK / 128);
        gemm_qkv_rope<<<grid, 128>>>(hidp, wqkvp, pos_xyz, q, ks, vt);
    }

    // 2. Flash attention
    {
        cudaFuncSetAttribute(flash_attn_tf32,
                             cudaFuncAttributeMaxDynamicSharedMemorySize,
                             FA_SMEM_BYTES);
        dim3 grid(S_LEN / 64, BB * NH);
        flash_attn_tf32<<<grid, 128, FA_SMEM_BYTES>>>(
            q, (const uint2*)ks, (const uint2*)vt, lens, ao);
    }

    // 3. Output projection (plain, R13 config)
    {
        dim3 grid(DM / 64, M_TOK / 128);
        gemm_out<<<grid, 128>>>(ao, woutp, out, DM, DM);
    }
}